// round 10
// baseline (speedup 1.0000x reference)
#include <cuda_runtime.h>
#include <math.h>

#define BB   16
#define NN   2048
#define DD   128
#define NSL  8
#define HH   128
#define RWS  (BB*NSL)            // 128 slot rows
#define EPSV 1e-8f
#define CH   64                  // n-rows per kStep chunk
#define KSTR 33                  // float4 stride for ks rows

// ---------------- scratch (__device__ globals: allocation-free) ----------------
__device__ float g_k[BB*NN*DD];          // 16 MB, k == v
__device__ float g_mus[RWS*DD];          // mu_s (GRU hidden)
__device__ float g_wa[RWS*DD];           // inv_var
__device__ float g_wb[RWS*DD];           // -2*inv*qmu
__device__ float g_wc[RWS];              // sum inv*qmu^2
__device__ float g_pi[RWS];
__device__ float g_gsum[RWS];
__device__ float g_accV[RWS*DD];
__device__ float g_accV2[RWS*DD];
__device__ unsigned g_cnt[BB];

// transposed weights
__device__ float g_WkT[DD*DD];           // [kk][c]
__device__ float g_WqT[DD*DD];           // [c][d]
__device__ float g_WihT[DD*3*DD];        // [c][j]
__device__ float g_WhhT[DD*3*DD];
__device__ float g_W1muT[DD*HH];         // [c][j]
__device__ float g_W2muT[HH*DD];         // [j][d]
__device__ float g_W1oT[2*DD*2*HH];      // [c][j]
__device__ float g_W2oT[2*HH*DD];        // [c][d]

__device__ __forceinline__ float sigmf(float x) { return 1.f/(1.f+expf(-x)); }

// ---------------- kNop: keeps ncu's -s 5 window on kStep #2 ----------------
__global__ void kNop() {}

// ---------------- kT: one-time weight transposes + counter zero ----------------
__global__ void kT(const float* __restrict__ Wk, const float* __restrict__ Wq,
                   const float* __restrict__ Wih, const float* __restrict__ Whh,
                   const float* __restrict__ W1mu, const float* __restrict__ W2mu,
                   const float* __restrict__ W1o, const float* __restrict__ W2o) {
  int tid = blockIdx.x*blockDim.x + threadIdx.x;
  int stride = gridDim.x*blockDim.x;
  if (tid < BB) g_cnt[tid] = 0u;
  for (int i=tid;i<DD*DD;i+=stride){int c=i>>7,kk=i&127; g_WkT[kk*DD+c]=Wk[i];}
  for (int i=tid;i<DD*DD;i+=stride){int d=i>>7,c=i&127;  g_WqT[c*DD+d]=Wq[i];}
  for (int i=tid;i<3*DD*DD;i+=stride){int j=i>>7,c=i&127; g_WihT[c*384+j]=Wih[i]; g_WhhT[c*384+j]=Whh[i];}
  for (int i=tid;i<HH*DD;i+=stride){int j=i>>7,c=i&127;  g_W1muT[c*HH+j]=W1mu[i];}
  for (int i=tid;i<DD*HH;i+=stride){int d=i>>7,j=i&127;  g_W2muT[j*DD+d]=W2mu[i];}
  for (int i=tid;i<2*HH*2*DD;i+=stride){int j=i>>8,c=i&255; g_W1oT[c*256+j]=W1o[i];}
  for (int i=tid;i<DD*2*HH;i+=stride){int d=i>>8,c=i&255; g_W2oT[c*DD+d]=W2o[i];}
}

// ---------------- kA: fused LayerNorm + k = xn @ Wk^T ----------------
__global__ void kA(const float* __restrict__ inp,
                   const float* __restrict__ lng, const float* __restrict__ lnb) {
  __shared__ float xs[64*DD];
  __shared__ float wt[16*DD];
  const int tid = threadIdx.x;
  const int r0blk = blockIdx.x*64;
  for (int idx=tid; idx<64*DD; idx+=256) xs[idx] = inp[(long)r0blk*DD + idx];
  __syncthreads();
  { // LayerNorm: warp w -> rows w*8..w*8+7
    int w = tid>>5, lane = tid&31;
    for (int r=w*8; r<w*8+8; ++r) {
      float x0=xs[r*DD+lane],    x1=xs[r*DD+lane+32];
      float x2=xs[r*DD+lane+64], x3=xs[r*DD+lane+96];
      float s = x0+x1+x2+x3;
      #pragma unroll
      for (int o=16;o;o>>=1) s += __shfl_xor_sync(0xffffffffu,s,o);
      float m = s*(1.f/128.f);
      float d0=x0-m,d1=x1-m,d2=x2-m,d3=x3-m;
      float s2 = d0*d0+d1*d1+d2*d2+d3*d3;
      #pragma unroll
      for (int o=16;o;o>>=1) s2 += __shfl_xor_sync(0xffffffffu,s2,o);
      float rs = rsqrtf(s2*(1.f/128.f)+1e-5f);
      xs[r*DD+lane]    = d0*rs*lng[lane]    + lnb[lane];
      xs[r*DD+lane+32] = d1*rs*lng[lane+32] + lnb[lane+32];
      xs[r*DD+lane+64] = d2*rs*lng[lane+64] + lnb[lane+64];
      xs[r*DD+lane+96] = d3*rs*lng[lane+96] + lnb[lane+96];
    }
  }
  const int cg = tid&31, rg = tid>>5;
  const int c0 = cg*4, r0 = rg*8;
  float4 acc[8];
  #pragma unroll
  for (int r=0;r<8;++r) acc[r] = make_float4(0.f,0.f,0.f,0.f);
  for (int kt=0; kt<8; ++kt) {
    __syncthreads();
    for (int i=tid; i<16*DD; i+=256) wt[i] = g_WkT[kt*16*DD + i];
    __syncthreads();
    #pragma unroll 4
    for (int kk=0;kk<16;++kk) {
      float4 wv = *(const float4*)&wt[kk*DD+c0];
      int kg = kt*16 + kk;
      #pragma unroll
      for (int r=0;r<8;++r) {
        float xv = xs[(r0+r)*DD+kg];
        acc[r].x = fmaf(xv,wv.x,acc[r].x);
        acc[r].y = fmaf(xv,wv.y,acc[r].y);
        acc[r].z = fmaf(xv,wv.z,acc[r].z);
        acc[r].w = fmaf(xv,wv.w,acc[r].w);
      }
    }
  }
  #pragma unroll
  for (int r=0;r<8;++r)
    *(float4*)&g_k[(long)(r0blk + r0 + r)*DD + c0] = acc[r];
}

// ---------------- 8-warp block reduce ----------------
__device__ __forceinline__ float blkSum8(float v, float* red, int tid) {
  int lane = tid&31, w = tid>>5;
  #pragma unroll
  for (int o=16;o;o>>=1) v += __shfl_xor_sync(0xffffffffu,v,o);
  if (lane==0) red[w] = v;
  __syncthreads();
  float tot = red[0]+red[1]+red[2]+red[3]+red[4]+red[5]+red[6]+red[7];
  __syncthreads();
  return tot;
}

// ---------------- kInit: slot init + pi + first Q-phase ----------------
__global__ void kInit(const float* __restrict__ noise, const float* __restrict__ smu,
                      const float* __restrict__ slsig,
                      const float* __restrict__ lsg, const float* __restrict__ lsb) {
  __shared__ float sv[256];
  __shared__ float sn[256];
  __shared__ float tmp[128];
  __shared__ float red[8];
  int r = blockIdx.x, t = threadIdx.x;
  sv[t] = smu[t] + expf(slsig[t])*noise[r*256+t];
  if (t==0) g_pi[r] = 1.f/(float)NSL;
  __syncthreads();
  float x = sv[t];
  float m = blkSum8(x, red, t) * (1.f/256.f);
  float dv = x - m;
  float var = blkSum8(dv*dv, red, t) * (1.f/256.f);
  float rs = rsqrtf(var + 1e-5f);
  sn[t] = dv*rs*lsg[t] + lsb[t];
  __syncthreads();
  int idx = t & 127;
  const float* s = (t < 128) ? &sn[0] : &sn[128];
  float acc = 0.f;
  #pragma unroll 16
  for (int c=0;c<128;++c) acc = fmaf(s[c], g_WqT[c*DD+idx], acc);
  if (t >= 128) {
    float inv = expf(-2.f*acc);
    g_wa[r*DD+idx] = inv;
    tmp[idx] = inv;
  }
  __syncthreads();
  float cpart = 0.f;
  if (t < 128) {
    float inv = tmp[t];
    g_wb[r*DD+t] = -2.f*inv*acc;
    g_mus[r*DD+t] = sn[t];
    g_accV[r*DD+t] = 0.f;
    g_accV2[r*DD+t] = 0.f;
    cpart = inv*acc*acc;
  }
  float C = blkSum8(cpart, red, t);
  if (t==0) { g_wc[r] = C; g_gsum[r] = 0.f; }
}

// ---------------- kStep: kP + fused per-batch finisher (last-block-done) -------
// grid (16 b, 32 chunks of 64 n), 256 threads; SM = 46336 B flat shared buffer
__global__ void __launch_bounds__(256, 4) kStep(
    const float* __restrict__ bih, const float* __restrict__ bhh,
    const float* __restrict__ b1, const float* __restrict__ b2,
    const float* __restrict__ lmg, const float* __restrict__ lmb,
    const float* __restrict__ lsg, const float* __restrict__ lsb,
    const float* __restrict__ b1o, const float* __restrict__ b2o,
    float* __restrict__ outp, int last) {
  __shared__ __align__(16) float SM[11584];
  __shared__ float sC[8], sPi[8], sgs[8], swc[8];
  __shared__ unsigned sLast;
  float4* ks4 = (float4*)SM;               // 64 rows x KSTR float4 (8448 floats)
  float4* wa4 = (float4*)(SM + 8448);      // 8 x KSTR float4 (1056)
  float4* wb4 = (float4*)(SM + 9504);      // 1056
  float* pd   = SM + 10560;                // 512
  float* gm   = SM + 11072;                // 512
  int b = blockIdx.x, chunk = blockIdx.y;
  int tid = threadIdx.x, lane = tid&31, w = tid>>5;
  { // stage wa/wb
    int s = tid>>5, i = tid&31;
    wa4[s*KSTR+i] = ((const float4*)&g_wa[(b*8+s)*DD])[i];
    wb4[s*KSTR+i] = ((const float4*)&g_wb[(b*8+s)*DD])[i];
  }
  if (tid<8) { sC[tid] = g_wc[b*8+tid]; sPi[tid] = g_pi[b*8+tid]; }
  for (int i=tid; i<512; i+=256) pd[i] = 0.f;
  { // stage k tile
    const float4* src = (const float4*)&g_k[(long)b*NN*DD + (long)chunk*CH*DD];
    #pragma unroll
    for (int rep=0; rep<8; ++rep) {
      int i = rep*256 + tid;
      ks4[(i>>5)*KSTR + (i&31)] = src[i];
    }
  }
  __syncthreads();
  // phase 1: thread = (n = tid&63, dq = tid>>6)
  {
    int n = tid&63, dq = tid>>6;
    float acc[8];
    #pragma unroll
    for (int s=0;s<8;++s) acc[s]=0.f;
    const float4* kr = &ks4[n*KSTR + dq*8];
    #pragma unroll
    for (int i=0;i<8;++i) {
      float4 k4 = kr[i];
      #pragma unroll
      for (int s=0;s<8;++s) {
        float4 a4 = wa4[s*KSTR + dq*8 + i];
        float4 b4 = wb4[s*KSTR + dq*8 + i];
        float p = fmaf(a4.x,k4.x,b4.x)*k4.x;
        p = fmaf(fmaf(a4.y,k4.y,b4.y), k4.y, p);
        p = fmaf(fmaf(a4.z,k4.z,b4.z), k4.z, p);
        p = fmaf(fmaf(a4.w,k4.w,b4.w), k4.w, p);
        acc[s] += p;
      }
    }
    #pragma unroll
    for (int s=0;s<8;++s) atomicAdd(&pd[s*64+n], acc[s]);
  }
  __syncthreads();
  // phase 1b: softmax over slots
  if (tid < 64) {
    int n = tid;
    float e[8], ssum = 0.f;
    #pragma unroll
    for (int s=0;s<8;++s) {
      float dot = pd[s*64+n] + sC[s];
      e[s] = (expf(-dot) + EPSV) * sPi[s];
      ssum += e[s];
    }
    float inv = 1.f/ssum;
    #pragma unroll
    for (int s=0;s<8;++s) gm[n*8+s] = e[s]*inv;
  }
  __syncthreads();
  // phase 2: warp = (slot-pair, n-half)
  {
    int sp = w & 3, nh = w >> 2;
    int s0 = sp*2, s1 = sp*2+1;
    float4 aV0 = make_float4(0,0,0,0), a20 = make_float4(0,0,0,0);
    float4 aV1 = make_float4(0,0,0,0), a21 = make_float4(0,0,0,0);
    float gs0 = 0.f, gs1 = 0.f;
    #pragma unroll 4
    for (int ni=0; ni<32; ++ni) {
      int n = nh*32 + ni;
      float4 k4 = ks4[n*KSTR+lane];
      float2 g2 = *(const float2*)&gm[n*8 + s0];
      float g0 = g2.x, g1 = g2.y;
      gs0 += g0; gs1 += g1;
      float sx = k4.x*k4.x, sy = k4.y*k4.y, sz = k4.z*k4.z, sw = k4.w*k4.w;
      aV0.x = fmaf(g0,k4.x,aV0.x); aV0.y = fmaf(g0,k4.y,aV0.y);
      aV0.z = fmaf(g0,k4.z,aV0.z); aV0.w = fmaf(g0,k4.w,aV0.w);
      a20.x = fmaf(g0,sx,a20.x); a20.y = fmaf(g0,sy,a20.y);
      a20.z = fmaf(g0,sz,a20.z); a20.w = fmaf(g0,sw,a20.w);
      aV1.x = fmaf(g1,k4.x,aV1.x); aV1.y = fmaf(g1,k4.y,aV1.y);
      aV1.z = fmaf(g1,k4.z,aV1.z); aV1.w = fmaf(g1,k4.w,aV1.w);
      a21.x = fmaf(g1,sx,a21.x); a21.y = fmaf(g1,sy,a21.y);
      a21.z = fmaf(g1,sz,a21.z); a21.w = fmaf(g1,sw,a21.w);
    }
    float* pV0 = &g_accV [(b*8+s0)*DD + lane*4];
    float* p20 = &g_accV2[(b*8+s0)*DD + lane*4];
    float* pV1 = &g_accV [(b*8+s1)*DD + lane*4];
    float* p21 = &g_accV2[(b*8+s1)*DD + lane*4];
    atomicAdd(pV0+0,aV0.x); atomicAdd(pV0+1,aV0.y);
    atomicAdd(pV0+2,aV0.z); atomicAdd(pV0+3,aV0.w);
    atomicAdd(p20+0,a20.x); atomicAdd(p20+1,a20.y);
    atomicAdd(p20+2,a20.z); atomicAdd(p20+3,a20.w);
    atomicAdd(pV1+0,aV1.x); atomicAdd(pV1+1,aV1.y);
    atomicAdd(pV1+2,aV1.z); atomicAdd(pV1+3,aV1.w);
    atomicAdd(p21+0,a21.x); atomicAdd(p21+1,a21.y);
    atomicAdd(p21+2,a21.z); atomicAdd(p21+3,a21.w);
    if (lane==0) { atomicAdd(&g_gsum[b*8+s0], gs0); atomicAdd(&g_gsum[b*8+s1], gs1); }
  }
  // ---- last-block detection ----
  __threadfence();
  __syncthreads();
  if (tid==0) sLast = (atomicAdd(&g_cnt[b], 1u) == 31u) ? 1u : 0u;
  __syncthreads();
  if (!sLast) return;
  __threadfence();
  // ================= FINISHER: slot update for rows b*8..b*8+7 =================
  float* fs   = SM;
  float* s1s  = fs;            // 1024  [q*128+d]
  float* s2s  = fs + 1024;
  float* mus  = fs + 2048;
  float* ups  = fs + 3072;
  float* stage= fs + 4096;     // 3072 scratch
  float* hs   = fs + 7168;     // 1024
  float* sn8  = SM + 8448;     // 2048  [q*256+d]
  float* tmpv = SM + 10560;    // 1024
  int r0 = b*8;
  int j = tid & 127, th = tid >> 7;
  if (tid<8) { sgs[tid] = __ldcg(&g_gsum[r0+tid]); swc[tid] = 0.f; }
  __syncthreads();
  for (int i=tid; i<1024; i+=256) {
    int q = i>>7;
    float gi = 1.f/sgs[q];
    s1s[i] = __ldcg(&g_accV [r0*DD + i]) * gi;
    s2s[i] = __ldcg(&g_accV2[r0*DD + i]) * gi;
    mus[i] = g_mus[r0*DD + i];
  }
  __syncthreads();
  // GRU: 2 passes of 4 rows; th=0 input gates (from s1s), th=1 hidden (from mus)
  for (int p=0; p<2; ++p) {
    {
      const float* W   = th ? g_WhhT : g_WihT;
      const float* src = (th ? mus : s1s) + p*512;
      float a[12];
      #pragma unroll
      for (int i=0;i<12;++i) a[i]=0.f;
      #pragma unroll 4
      for (int c=0;c<128;++c) {
        float w0 = W[c*384+j], w1 = W[c*384+128+j], w2 = W[c*384+256+j];
        #pragma unroll
        for (int q=0;q<4;++q) {
          float x = src[q*128+c];
          a[q]   = fmaf(w0,x,a[q]);
          a[4+q] = fmaf(w1,x,a[4+q]);
          a[8+q] = fmaf(w2,x,a[8+q]);
        }
      }
      #pragma unroll
      for (int g=0;g<3;++g)
        #pragma unroll
        for (int q=0;q<4;++q)
          stage[th*1536 + g*512 + q*128 + j] = a[g*4+q];
    }
    __syncthreads();
    #pragma unroll
    for (int rep=0; rep<2; ++rep) {
      int u = rep*256 + tid;          // 512 outputs: 4 rows x 128
      int q4 = u>>7, jj = u&127, q = p*4 + q4;
      float Gir = stage[       q4*128+jj] + bih[jj];
      float Giz = stage[ 512 + q4*128+jj] + bih[128+jj];
      float Gin = stage[1024 + q4*128+jj] + bih[256+jj];
      float Ghr = stage[1536 + q4*128+jj] + bhh[jj];
      float Ghz = stage[2048 + q4*128+jj] + bhh[128+jj];
      float Ghn = stage[2560 + q4*128+jj] + bhh[256+jj];
      float rg = sigmf(Gir+Ghr);
      float zg = sigmf(Giz+Ghz);
      float ng = tanhf(Gin + rg*Ghn);
      ups[q*128+jj] = (1.f-zg)*ng + zg*mus[q*128+jj];
    }
    __syncthreads();
  }
  // LN(ups): warp w -> row w
  {
    float x0=ups[w*128+lane], x1=ups[w*128+lane+32];
    float x2=ups[w*128+lane+64], x3=ups[w*128+lane+96];
    float s = x0+x1+x2+x3;
    #pragma unroll
    for (int o=16;o;o>>=1) s += __shfl_xor_sync(0xffffffffu,s,o);
    float m = s*(1.f/128.f);
    float d0=x0-m,d1=x1-m,d2=x2-m,d3=x3-m;
    float s2 = d0*d0+d1*d1+d2*d2+d3*d3;
    #pragma unroll
    for (int o=16;o;o>>=1) s2 += __shfl_xor_sync(0xffffffffu,s2,o);
    float rs = rsqrtf(s2*(1.f/128.f)+1e-5f);
    hs[w*128+lane]    = d0*rs*lmg[lane]    + lmb[lane];
    hs[w*128+lane+32] = d1*rs*lmg[lane+32] + lmb[lane+32];
    hs[w*128+lane+64] = d2*rs*lmg[lane+64] + lmb[lane+64];
    hs[w*128+lane+96] = d3*rs*lmg[lane+96] + lmb[lane+96];
  }
  __syncthreads();
  // MLP1: 8 rows, c split over th
  {
    float a[8];
    #pragma unroll
    for (int q=0;q<8;++q) a[q]=0.f;
    int c0 = th*64;
    #pragma unroll 8
    for (int c=c0; c<c0+64; ++c) {
      float wv = g_W1muT[c*HH+j];
      #pragma unroll
      for (int q=0;q<8;++q) a[q] = fmaf(hs[q*128+c], wv, a[q]);
    }
    #pragma unroll
    for (int q=0;q<8;++q) stage[th*1024 + q*128 + j] = a[q];
  }
  __syncthreads();
  #pragma unroll
  for (int rep=0; rep<4; ++rep) {
    int u = rep*256 + tid, jj = u&127;
    stage[u] = fmaxf(stage[u] + stage[1024+u] + b1[jj], 0.f);  // m1 in stage[0:1024)
  }
  __syncthreads();
  // MLP2: 8 rows, hidden-j split over th
  {
    float a[8];
    #pragma unroll
    for (int q=0;q<8;++q) a[q]=0.f;
    int j0 = th*64;
    #pragma unroll 8
    for (int c=j0; c<j0+64; ++c) {
      float wv = g_W2muT[c*DD+j];
      #pragma unroll
      for (int q=0;q<8;++q) a[q] = fmaf(stage[q*128+c], wv, a[q]);
    }
    #pragma unroll
    for (int q=0;q<8;++q) stage[1024 + th*1024 + q*128 + j] = a[q];
  }
  __syncthreads();
  // combine -> out, ls (registers), then write sv over stage
  float outv[4], lsv[4];
  #pragma unroll
  for (int rep=0; rep<4; ++rep) {
    int u = rep*256 + tid;
    int q = u>>7, dd = u&127;
    float o = ups[q*128+dd] + b2[dd] + stage[1024+u] + stage[2048+u];
    outv[rep] = o;
    lsv[rep] = 0.5f*logf(s2s[u] - 2.f*o*s1s[u] + o*o + EPSV);
  }
  __syncthreads();
  float* sv = stage;   // [q*256+d2], 2048
  #pragma unroll
  for (int rep=0; rep<4; ++rep) {
    int u = rep*256 + tid;
    int q = u>>7, dd = u&127;
    sv[q*256+dd]     = outv[rep];
    sv[q*256+128+dd] = lsv[rep];
  }
  if (tid<8) g_pi[r0+tid] = sgs[tid];
  __syncthreads();
  if (!last) {
    // Q-phase for 8 rows: LN per warp-row, then Wq
    {
      float x[8], dx[8];
      float s = 0.f;
      #pragma unroll
      for (int i=0;i<8;++i) { x[i] = sv[w*256 + lane + 32*i]; s += x[i]; }
      #pragma unroll
      for (int o=16;o;o>>=1) s += __shfl_xor_sync(0xffffffffu,s,o);
      float m = s*(1.f/256.f);
      float s2 = 0.f;
      #pragma unroll
      for (int i=0;i<8;++i) { dx[i] = x[i]-m; s2 += dx[i]*dx[i]; }
      #pragma unroll
      for (int o=16;o;o>>=1) s2 += __shfl_xor_sync(0xffffffffu,s2,o);
      float rs = rsqrtf(s2*(1.f/256.f)+1e-5f);
      #pragma unroll
      for (int i=0;i<8;++i)
        sn8[w*256 + lane + 32*i] = dx[i]*rs*lsg[lane+32*i] + lsb[lane+32*i];
    }
    __syncthreads();
    float a[8];
    #pragma unroll
    for (int q=0;q<8;++q) a[q]=0.f;
    #pragma unroll 8
    for (int c=0;c<128;++c) {
      float wv = g_WqT[c*DD+j];
      #pragma unroll
      for (int q=0;q<8;++q) a[q] = fmaf(sn8[q*256 + th*128 + c], wv, a[q]);
    }
    if (th==1) {
      #pragma unroll
      for (int q=0;q<8;++q) {
        float inv = expf(-2.f*a[q]);
        g_wa[(r0+q)*DD+j] = inv;
        tmpv[q*128+j] = inv;
      }
    }
    __syncthreads();
    if (th==0) {
      float cp[8];
      #pragma unroll
      for (int q=0;q<8;++q) {
        float inv = tmpv[q*128+j];
        g_wb[(r0+q)*DD+j]  = -2.f*inv*a[q];
        g_mus[(r0+q)*DD+j] = sn8[q*256+j];
        g_accV[(r0+q)*DD+j]  = 0.f;
        g_accV2[(r0+q)*DD+j] = 0.f;
        cp[q] = inv*a[q]*a[q];
      }
      #pragma unroll
      for (int q=0;q<8;++q) {
        float v = cp[q];
        #pragma unroll
        for (int o=16;o;o>>=1) v += __shfl_xor_sync(0xffffffffu,v,o);
        if (lane==0) atomicAdd(&swc[q], v);
      }
    }
    __syncthreads();
    if (tid<8) { g_wc[r0+tid] = swc[tid]; g_gsum[r0+tid] = 0.f; }
  } else {
    // final output MLP for 8 rows
    float* h8 = fs;  // 2048, s1s/s2s dead
    {
      float a[8];
      #pragma unroll
      for (int q=0;q<8;++q) a[q]=0.f;
      #pragma unroll 8
      for (int c=0;c<256;++c) {
        float wv = g_W1oT[c*256+tid];
        #pragma unroll
        for (int q=0;q<8;++q) a[q] = fmaf(sv[q*256+c], wv, a[q]);
      }
      __syncthreads();
      #pragma unroll
      for (int q=0;q<8;++q) h8[q*256+tid] = fmaxf(a[q]+b1o[tid], 0.f);
    }
    __syncthreads();
    {
      float a[8];
      #pragma unroll
      for (int q=0;q<8;++q) a[q]=0.f;
      int c0 = th*128;
      #pragma unroll 8
      for (int c=c0; c<c0+128; ++c) {
        float wv = g_W2oT[c*DD+j];
        #pragma unroll
        for (int q=0;q<8;++q) a[q] = fmaf(h8[q*256+c], wv, a[q]);
      }
      #pragma unroll
      for (int q=0;q<8;++q) sn8[th*1024 + q*128 + j] = a[q];
    }
    __syncthreads();
    #pragma unroll
    for (int rep=0; rep<4; ++rep) {
      int u = rep*256 + tid;
      int q = u>>7, dd = u&127;
      outp[(r0+q)*DD+dd] = sn8[u] + sn8[1024+u] + b2o[dd];
    }
  }
  if (tid==0) g_cnt[b] = 0u;
}

extern "C" void kernel_launch(void* const* d_in, const int* in_sizes, int n_in,
                              void* d_out, int out_size) {
  const float* inputs  = (const float*)d_in[0];
  const float* noise   = (const float*)d_in[1];
  const float* smu     = (const float*)d_in[2];
  const float* slsig   = (const float*)d_in[3];
  const float* Wq      = (const float*)d_in[4];
  const float* Wk      = (const float*)d_in[5];
  const float* Wih     = (const float*)d_in[6];
  const float* Whh     = (const float*)d_in[7];
  const float* bih     = (const float*)d_in[8];
  const float* bhh     = (const float*)d_in[9];
  const float* W1mu    = (const float*)d_in[10];
  const float* b1mu    = (const float*)d_in[11];
  const float* W2mu    = (const float*)d_in[12];
  const float* b2mu    = (const float*)d_in[13];
  const float* ln_in_g = (const float*)d_in[14];
  const float* ln_in_b = (const float*)d_in[15];
  const float* lsg     = (const float*)d_in[16];
  const float* lsb     = (const float*)d_in[17];
  const float* lmg     = (const float*)d_in[18];
  const float* lmb     = (const float*)d_in[19];
  const float* W1o     = (const float*)d_in[20];
  const float* b1o     = (const float*)d_in[21];
  const float* W2o     = (const float*)d_in[22];
  const float* b2o     = (const float*)d_in[23];
  float* out = (float*)d_out;

  kNop<<<1, 32>>>();
  kT<<<64, 256>>>(Wk, Wq, Wih, Whh, W1mu, W2mu, W1o, W2o);
  kA<<<(BB*NN)/64, 256>>>(inputs, ln_in_g, ln_in_b);
  kInit<<<RWS, 256>>>(noise, smu, slsig, lsg, lsb);
  for (int it=0; it<4; ++it) {
    kStep<<<dim3(BB, NN/CH), 256>>>(bih, bhh, b1mu, b2mu, lmg, lmb, lsg, lsb,
                                    b1o, b2o, out, it==3 ? 1 : 0);
  }
}

// round 11
// speedup vs baseline: 1.4917x; 1.4917x over previous
#include <cuda_runtime.h>
#include <math.h>

#define BB   16
#define NN   2048
#define DD   128
#define NSL  8
#define HH   128
#define RWS  (BB*NSL)            // 128 slot rows
#define EPSV 1e-8f
#define CH   64                  // n-rows per kP chunk
#define KSTR 33                  // float4 stride for ks rows

// ---------------- scratch (__device__ globals: allocation-free) ----------------
__device__ float g_k[BB*NN*DD];          // 16 MB, k == v
__device__ float g_mus[RWS*DD];          // mu_s (GRU hidden)
__device__ float g_wa[RWS*DD];           // inv_var
__device__ float g_wb[RWS*DD];           // -2*inv*qmu
__device__ float g_wc[RWS];              // sum inv*qmu^2
__device__ float g_pi[RWS];
__device__ float g_gsum[RWS];
__device__ float g_accV[RWS*DD];
__device__ float g_accV2[RWS*DD];

// transposed weights
__device__ float g_WkT[DD*DD];           // [kk][c]
__device__ float g_WqT[DD*DD];           // [c][d]
__device__ float g_WihT[DD*3*DD];        // [c][j]
__device__ float g_WhhT[DD*3*DD];
__device__ float g_W1muT[DD*HH];         // [c][j]
__device__ float g_W2muT[HH*DD];         // [j][d]
__device__ float g_W1oT[2*DD*2*HH];      // [c][j]
__device__ float g_W2oT[2*HH*DD];        // [c][d]

// ---------------- kT: one-time weight transposes ----------------
__global__ void kT(const float* __restrict__ Wk, const float* __restrict__ Wq,
                   const float* __restrict__ Wih, const float* __restrict__ Whh,
                   const float* __restrict__ W1mu, const float* __restrict__ W2mu,
                   const float* __restrict__ W1o, const float* __restrict__ W2o) {
  int tid = blockIdx.x*blockDim.x + threadIdx.x;
  int stride = gridDim.x*blockDim.x;
  for (int i=tid;i<DD*DD;i+=stride){int c=i>>7,kk=i&127; g_WkT[kk*DD+c]=Wk[i];}
  for (int i=tid;i<DD*DD;i+=stride){int d=i>>7,c=i&127;  g_WqT[c*DD+d]=Wq[i];}
  for (int i=tid;i<3*DD*DD;i+=stride){int j=i>>7,c=i&127; g_WihT[c*384+j]=Wih[i]; g_WhhT[c*384+j]=Whh[i];}
  for (int i=tid;i<HH*DD;i+=stride){int j=i>>7,c=i&127;  g_W1muT[c*HH+j]=W1mu[i];}
  for (int i=tid;i<DD*HH;i+=stride){int d=i>>7,j=i&127;  g_W2muT[j*DD+d]=W2mu[i];}
  for (int i=tid;i<2*HH*2*DD;i+=stride){int j=i>>8,c=i&255; g_W1oT[c*256+j]=W1o[i];}
  for (int i=tid;i<DD*2*HH;i+=stride){int d=i>>8,c=i&255; g_W2oT[c*DD+d]=W2o[i];}
}

// ---------------- kA: fused LayerNorm + k = xn @ Wk^T ----------------
__global__ void kA(const float* __restrict__ inp,
                   const float* __restrict__ lng, const float* __restrict__ lnb) {
  __shared__ float xs[64*DD];
  __shared__ float wt[16*DD];
  const int tid = threadIdx.x;
  const int r0blk = blockIdx.x*64;
  for (int idx=tid; idx<64*DD; idx+=256) xs[idx] = inp[(long)r0blk*DD + idx];
  __syncthreads();
  { // LayerNorm: warp w -> rows w*8..w*8+7
    int w = tid>>5, lane = tid&31;
    for (int r=w*8; r<w*8+8; ++r) {
      float x0=xs[r*DD+lane],    x1=xs[r*DD+lane+32];
      float x2=xs[r*DD+lane+64], x3=xs[r*DD+lane+96];
      float s = x0+x1+x2+x3;
      #pragma unroll
      for (int o=16;o;o>>=1) s += __shfl_xor_sync(0xffffffffu,s,o);
      float m = s*(1.f/128.f);
      float d0=x0-m,d1=x1-m,d2=x2-m,d3=x3-m;
      float s2 = d0*d0+d1*d1+d2*d2+d3*d3;
      #pragma unroll
      for (int o=16;o;o>>=1) s2 += __shfl_xor_sync(0xffffffffu,s2,o);
      float rs = rsqrtf(s2*(1.f/128.f)+1e-5f);
      xs[r*DD+lane]    = d0*rs*lng[lane]    + lnb[lane];
      xs[r*DD+lane+32] = d1*rs*lng[lane+32] + lnb[lane+32];
      xs[r*DD+lane+64] = d2*rs*lng[lane+64] + lnb[lane+64];
      xs[r*DD+lane+96] = d3*rs*lng[lane+96] + lnb[lane+96];
    }
  }
  const int cg = tid&31, rg = tid>>5;
  const int c0 = cg*4, r0 = rg*8;
  float4 acc[8];
  #pragma unroll
  for (int r=0;r<8;++r) acc[r] = make_float4(0.f,0.f,0.f,0.f);
  for (int kt=0; kt<8; ++kt) {
    __syncthreads();
    for (int i=tid; i<16*DD; i+=256) wt[i] = g_WkT[kt*16*DD + i];
    __syncthreads();
    #pragma unroll 4
    for (int kk=0;kk<16;++kk) {
      float4 wv = *(const float4*)&wt[kk*DD+c0];
      int kg = kt*16 + kk;
      #pragma unroll
      for (int r=0;r<8;++r) {
        float xv = xs[(r0+r)*DD+kg];
        acc[r].x = fmaf(xv,wv.x,acc[r].x);
        acc[r].y = fmaf(xv,wv.y,acc[r].y);
        acc[r].z = fmaf(xv,wv.z,acc[r].z);
        acc[r].w = fmaf(xv,wv.w,acc[r].w);
      }
    }
  }
  #pragma unroll
  for (int r=0;r<8;++r)
    *(float4*)&g_k[(long)(r0blk + r0 + r)*DD + c0] = acc[r];
}

// ---------------- 8-warp block reduce ----------------
__device__ __forceinline__ float blkSum8(float v, float* red, int tid) {
  int lane = tid&31, w = tid>>5;
  #pragma unroll
  for (int o=16;o;o>>=1) v += __shfl_xor_sync(0xffffffffu,v,o);
  if (lane==0) red[w] = v;
  __syncthreads();
  float tot = red[0]+red[1]+red[2]+red[3]+red[4]+red[5]+red[6]+red[7];
  __syncthreads();
  return tot;
}

// ---------------- Q-phase: LN(slots) + Wq -> wa/wb/wc, 256 threads, 1 row ------
__device__ __forceinline__ void qphase(int r, const float* sv, float* sn,
                                       float* tmp, float* red,
                                       const float* __restrict__ lsg,
                                       const float* __restrict__ lsb, int t) {
  float x = sv[t];
  float m = blkSum8(x, red, t) * (1.f/256.f);
  float dv = x - m;
  float var = blkSum8(dv*dv, red, t) * (1.f/256.f);
  float rs = rsqrtf(var + 1e-5f);
  sn[t] = dv*rs*lsg[t] + lsb[t];
  __syncthreads();
  int idx = t & 127;
  const float* s = (t < 128) ? &sn[0] : &sn[128];
  float acc = 0.f;
  #pragma unroll 16
  for (int c=0;c<128;++c) acc = fmaf(s[c], g_WqT[c*DD+idx], acc);
  if (t >= 128) {
    float inv = expf(-2.f*acc);
    g_wa[r*DD+idx] = inv;
    tmp[idx] = inv;
  }
  __syncthreads();
  float cpart = 0.f;
  if (t < 128) {
    float inv = tmp[t];
    g_wb[r*DD+t] = -2.f*inv*acc;
    g_mus[r*DD+t] = sn[t];
    g_accV[r*DD+t] = 0.f;
    g_accV2[r*DD+t] = 0.f;
    cpart = inv*acc*acc;
  }
  float C = blkSum8(cpart, red, t);
  if (t==0) { g_wc[r] = C; g_gsum[r] = 0.f; }
}

// ---------------- kInit: slot init + pi + first Q-phase ----------------
__global__ void kInit(const float* __restrict__ noise, const float* __restrict__ smu,
                      const float* __restrict__ slsig,
                      const float* __restrict__ lsg, const float* __restrict__ lsb) {
  __shared__ float sv[256];
  __shared__ float sn[256];
  __shared__ float tmp[128];
  __shared__ float red[8];
  int r = blockIdx.x, t = threadIdx.x;
  sv[t] = smu[t] + expf(slsig[t])*noise[r*256+t];
  if (t==0) g_pi[r] = 1.f/(float)NSL;
  __syncthreads();
  qphase(r, sv, sn, tmp, red, lsg, lsb, t);
}

// ---------------- kP: fused dots/gamma/moment pass -----------------------------
// grid (16 b, 32 chunks of 64 n), 256 threads; 46.3 KB static smem
// phase 1: thread = (n, slot-pair) over FULL d -- no cross-thread dot reduction
__global__ void __launch_bounds__(256, 4) kP() {
  __shared__ float4 ks4[CH*KSTR];          // 33792 B
  __shared__ float4 wa4[8*KSTR];           // 4224 B
  __shared__ float4 wb4[8*KSTR];           // 4224 B
  __shared__ float pd[8*64];               // 2048 B  [s][n] complete dots
  __shared__ float gm[CH*8];               // 2048 B  [n][s]
  __shared__ float sC[8], sPi[8];
  int b = blockIdx.x, chunk = blockIdx.y;
  int tid = threadIdx.x, lane = tid&31, w = tid>>5;
  { // stage wa/wb: 8 slots x 32 float4
    int s = tid>>5, i = tid&31;
    wa4[s*KSTR+i] = ((const float4*)&g_wa[(b*8+s)*DD])[i];
    wb4[s*KSTR+i] = ((const float4*)&g_wb[(b*8+s)*DD])[i];
  }
  if (tid<8) { sC[tid] = g_wc[b*8+tid]; sPi[tid] = g_pi[b*8+tid]; }
  { // stage k tile: 64 rows x 32 float4, coalesced
    const float4* src = (const float4*)&g_k[(long)b*NN*DD + (long)chunk*CH*DD];
    #pragma unroll
    for (int rep=0; rep<8; ++rep) {
      int i = rep*256 + tid;
      ks4[(i>>5)*KSTR + (i&31)] = src[i];
    }
  }
  __syncthreads();
  // phase 1: thread = (n = tid&63, sg = tid>>6); 2 complete dots over 128 d
  {
    int n = tid&63, sg = tid>>6;
    int s0 = sg*2, s1 = sg*2+1;
    const float4* kr  = &ks4[n*KSTR];
    const float4* wa0 = &wa4[s0*KSTR];
    const float4* wb0 = &wb4[s0*KSTR];
    const float4* wa1 = &wa4[s1*KSTR];
    const float4* wb1 = &wb4[s1*KSTR];
    float d0 = 0.f, d1 = 0.f;
    #pragma unroll 8
    for (int i=0;i<32;++i) {
      float4 k4 = kr[i];
      float4 a4 = wa0[i], b4 = wb0[i];
      float p = fmaf(a4.x,k4.x,b4.x)*k4.x;
      p = fmaf(fmaf(a4.y,k4.y,b4.y), k4.y, p);
      p = fmaf(fmaf(a4.z,k4.z,b4.z), k4.z, p);
      p = fmaf(fmaf(a4.w,k4.w,b4.w), k4.w, p);
      d0 += p;
      float4 a5 = wa1[i], b5 = wb1[i];
      float q = fmaf(a5.x,k4.x,b5.x)*k4.x;
      q = fmaf(fmaf(a5.y,k4.y,b5.y), k4.y, q);
      q = fmaf(fmaf(a5.z,k4.z,b5.z), k4.z, q);
      q = fmaf(fmaf(a5.w,k4.w,b5.w), k4.w, q);
      d1 += q;
    }
    pd[s0*64+n] = d0;
    pd[s1*64+n] = d1;
  }
  __syncthreads();
  // phase 1b: threads 0..63 (n) do exp + softmax over 8 slots
  if (tid < 64) {
    int n = tid;
    float e[8], ssum = 0.f;
    #pragma unroll
    for (int s=0;s<8;++s) {
      float dot = pd[s*64+n] + sC[s];
      e[s] = (expf(-dot) + EPSV) * sPi[s];
      ssum += e[s];
    }
    float inv = 1.f/ssum;
    #pragma unroll
    for (int s=0;s<8;++s) gm[n*8+s] = e[s]*inv;
  }
  __syncthreads();
  // phase 2: warp = (slot-pair, n-half); lane = d4
  {
    int sp = w & 3, nh = w >> 2;
    int s0 = sp*2, s1 = sp*2+1;
    float4 aV0 = make_float4(0,0,0,0), a20 = make_float4(0,0,0,0);
    float4 aV1 = make_float4(0,0,0,0), a21 = make_float4(0,0,0,0);
    float gs0 = 0.f, gs1 = 0.f;
    #pragma unroll 4
    for (int ni=0; ni<32; ++ni) {
      int n = nh*32 + ni;
      float4 k4 = ks4[n*KSTR+lane];
      float2 g2 = *(const float2*)&gm[n*8 + s0];
      float g0 = g2.x, g1 = g2.y;
      gs0 += g0; gs1 += g1;
      float sx = k4.x*k4.x, sy = k4.y*k4.y, sz = k4.z*k4.z, sw = k4.w*k4.w;
      aV0.x = fmaf(g0,k4.x,aV0.x); aV0.y = fmaf(g0,k4.y,aV0.y);
      aV0.z = fmaf(g0,k4.z,aV0.z); aV0.w = fmaf(g0,k4.w,aV0.w);
      a20.x = fmaf(g0,sx,a20.x); a20.y = fmaf(g0,sy,a20.y);
      a20.z = fmaf(g0,sz,a20.z); a20.w = fmaf(g0,sw,a20.w);
      aV1.x = fmaf(g1,k4.x,aV1.x); aV1.y = fmaf(g1,k4.y,aV1.y);
      aV1.z = fmaf(g1,k4.z,aV1.z); aV1.w = fmaf(g1,k4.w,aV1.w);
      a21.x = fmaf(g1,sx,a21.x); a21.y = fmaf(g1,sy,a21.y);
      a21.z = fmaf(g1,sz,a21.z); a21.w = fmaf(g1,sw,a21.w);
    }
    float* pV0 = &g_accV [(b*8+s0)*DD + lane*4];
    float* p20 = &g_accV2[(b*8+s0)*DD + lane*4];
    float* pV1 = &g_accV [(b*8+s1)*DD + lane*4];
    float* p21 = &g_accV2[(b*8+s1)*DD + lane*4];
    atomicAdd(pV0+0,aV0.x); atomicAdd(pV0+1,aV0.y);
    atomicAdd(pV0+2,aV0.z); atomicAdd(pV0+3,aV0.w);
    atomicAdd(p20+0,a20.x); atomicAdd(p20+1,a20.y);
    atomicAdd(p20+2,a20.z); atomicAdd(p20+3,a20.w);
    atomicAdd(pV1+0,aV1.x); atomicAdd(pV1+1,aV1.y);
    atomicAdd(pV1+2,aV1.z); atomicAdd(pV1+3,aV1.w);
    atomicAdd(p21+0,a21.x); atomicAdd(p21+1,a21.y);
    atomicAdd(p21+2,a21.z); atomicAdd(p21+3,a21.w);
    if (lane==0) { atomicAdd(&g_gsum[b*8+s0], gs0); atomicAdd(&g_gsum[b*8+s1], gs1); }
  }
}

// ---------------- kUQ: GRU + LN + MLP + logsigma, then Q-phase (or final MLP) ----
// 128 blocks (slot rows), 256 threads; GRU weights reg-double-buffered via smem
__global__ void kUQ(const float* __restrict__ bih, const float* __restrict__ bhh,
                    const float* __restrict__ b1, const float* __restrict__ b2,
                    const float* __restrict__ lmg, const float* __restrict__ lmb,
                    const float* __restrict__ lsg, const float* __restrict__ lsb,
                    const float* __restrict__ b1o, const float* __restrict__ b2o,
                    float* __restrict__ outp, int last) {
  __shared__ float swih[8*384];            // 12 KB weight stage
  __shared__ float swhh[8*384];            // 12 KB
  __shared__ float s1s[128], s2s[128], mus[128];
  __shared__ float ps[6*256];
  __shared__ float hs[128];
  __shared__ float m1[128];
  __shared__ float sv[256];
  __shared__ float sn[256];
  __shared__ float tmp[128];
  __shared__ float red[8];
  int r = blockIdx.x, t = threadIdx.x, tt = t & 127, th = t >> 7;
  float gsum = g_gsum[r];
  if (t < 128) {
    float inv = 1.f/gsum;
    s1s[t] = g_accV[r*DD+t]*inv;
    s2s[t] = g_accV2[r*DD+t]*inv;
    mus[t] = g_mus[r*DD+t];
  }
  __syncthreads();
  // GRU gates: 16 chunks of 8 c-rows, register double-buffered staging
  {
    const float4* giT = (const float4*)g_WihT;
    const float4* ghT = (const float4*)g_WhhT;
    float4 ri[3], rh[3];
    #pragma unroll
    for (int rep=0;rep<3;++rep) { ri[rep]=giT[rep*256+t]; rh[rep]=ghT[rep*256+t]; }
    float gir=0,giz=0,gin=0,ghr=0,ghz=0,ghn=0;
    for (int ch=0; ch<16; ++ch) {
      __syncthreads();
      #pragma unroll
      for (int rep=0;rep<3;++rep) {
        ((float4*)swih)[rep*256+t]=ri[rep];
        ((float4*)swhh)[rep*256+t]=rh[rep];
      }
      __syncthreads();
      if (ch<15) {
        #pragma unroll
        for (int rep=0;rep<3;++rep) {
          ri[rep]=giT[(ch+1)*768+rep*256+t];
          rh[rep]=ghT[(ch+1)*768+rep*256+t];
        }
      }
      int cl0 = th*4;
      #pragma unroll
      for (int ci=0; ci<4; ++ci) {
        int cl = cl0 + ci, c = ch*8 + cl;
        float xv = s1s[c], hv = mus[c];
        const float* wi = &swih[cl*384];
        const float* wh = &swhh[cl*384];
        gir = fmaf(xv, wi[tt],     gir);  ghr = fmaf(hv, wh[tt],     ghr);
        giz = fmaf(xv, wi[128+tt], giz);  ghz = fmaf(hv, wh[128+tt], ghz);
        gin = fmaf(xv, wi[256+tt], gin);  ghn = fmaf(hv, wh[256+tt], ghn);
      }
    }
    ps[t]=gir; ps[256+t]=giz; ps[512+t]=gin;
    ps[768+t]=ghr; ps[1024+t]=ghz; ps[1280+t]=ghn;
  }
  __syncthreads();
  float upd1 = 0.f;
  if (t < 128) {
    float Gir = ps[t]+ps[t+128]       + bih[t];
    float Giz = ps[256+t]+ps[384+t]   + bih[128+t];
    float Gin = ps[512+t]+ps[640+t]   + bih[256+t];
    float Ghr = ps[768+t]+ps[896+t]   + bhh[t];
    float Ghz = ps[1024+t]+ps[1152+t] + bhh[128+t];
    float Ghn = ps[1280+t]+ps[1408+t] + bhh[256+t];
    float rg = 1.f/(1.f+expf(-(Gir+Ghr)));
    float zg = 1.f/(1.f+expf(-(Giz+Ghz)));
    float ng = tanhf(Gin + rg*Ghn);
    upd1 = (1.f-zg)*ng + zg*mus[t];
  }
  __syncthreads();
  // LN(upd1) over 128 (inactive threads contribute 0)
  {
    float v = (t<128) ? upd1 : 0.f;
    float m = blkSum8(v, red, t) * (1.f/128.f);
    float dv = (t<128) ? (upd1 - m) : 0.f;
    float var = blkSum8(dv*dv, red, t) * (1.f/128.f);
    float rs = rsqrtf(var + 1e-5f);
    if (t<128) hs[t] = dv*rs*lmg[t] + lmb[t];
  }
  __syncthreads();
  // MLP1: split c over halves
  {
    float a = 0.f;
    int c0 = th*64;
    #pragma unroll 16
    for (int c=c0; c<c0+64; ++c) a = fmaf(hs[c], g_W1muT[c*HH+tt], a);
    ps[t] = a;
  }
  __syncthreads();
  if (t < 128) m1[t] = fmaxf(ps[t]+ps[t+128]+b1[t], 0.f);
  __syncthreads();
  // MLP2: split j over halves
  {
    float a = 0.f;
    int j0 = th*64;
    #pragma unroll 16
    for (int j=j0; j<j0+64; ++j) a = fmaf(m1[j], g_W2muT[j*DD+tt], a);
    ps[t] = a;
  }
  __syncthreads();
  if (t < 128) {
    float out = upd1 + b2[t] + ps[t] + ps[t+128];
    float ls = 0.5f*logf(s2s[t] - 2.f*out*s1s[t] + out*out + EPSV);
    sv[t] = out;
    sv[128+t] = ls;
    if (t==0) g_pi[r] = gsum;
  }
  __syncthreads();
  if (!last) {
    qphase(r, sv, sn, tmp, red, lsg, lsb, t);
  } else {
    // final output MLP: h = relu(sv @ W1o^T + b1o), out = h @ W2o^T + b2o
    float a = b1o[t];
    #pragma unroll 16
    for (int c=0;c<256;++c) a = fmaf(sv[c], g_W1oT[c*256+t], a);
    sn[t] = fmaxf(a, 0.f);
    __syncthreads();
    if (t < 128) {
      float o = b2o[t];
      #pragma unroll 16
      for (int c=0;c<256;++c) o = fmaf(sn[c], g_W2oT[c*DD+t], o);
      outp[r*DD+t] = o;
    }
  }
}

extern "C" void kernel_launch(void* const* d_in, const int* in_sizes, int n_in,
                              void* d_out, int out_size) {
  const float* inputs  = (const float*)d_in[0];
  const float* noise   = (const float*)d_in[1];
  const float* smu     = (const float*)d_in[2];
  const float* slsig   = (const float*)d_in[3];
  const float* Wq      = (const float*)d_in[4];
  const float* Wk      = (const float*)d_in[5];
  const float* Wih     = (const float*)d_in[6];
  const float* Whh     = (const float*)d_in[7];
  const float* bih     = (const float*)d_in[8];
  const float* bhh     = (const float*)d_in[9];
  const float* W1mu    = (const float*)d_in[10];
  const float* b1mu    = (const float*)d_in[11];
  const float* W2mu    = (const float*)d_in[12];
  const float* b2mu    = (const float*)d_in[13];
  const float* ln_in_g = (const float*)d_in[14];
  const float* ln_in_b = (const float*)d_in[15];
  const float* lsg     = (const float*)d_in[16];
  const float* lsb     = (const float*)d_in[17];
  const float* lmg     = (const float*)d_in[18];
  const float* lmb     = (const float*)d_in[19];
  const float* W1o     = (const float*)d_in[20];
  const float* b1o     = (const float*)d_in[21];
  const float* W2o     = (const float*)d_in[22];
  const float* b2o     = (const float*)d_in[23];
  float* out = (float*)d_out;

  kT<<<64, 256>>>(Wk, Wq, Wih, Whh, W1mu, W2mu, W1o, W2o);
  kA<<<(BB*NN)/64, 256>>>(inputs, ln_in_g, ln_in_b);
  kInit<<<RWS, 256>>>(noise, smu, slsig, lsg, lsb);
  for (int it=0; it<4; ++it) {
    kP<<<dim3(BB, NN/CH), 256>>>();
    kUQ<<<RWS, 256>>>(bih, bhh, b1mu, b2mu, lmg, lmb, lsg, lsb,
                      b1o, b2o, out, it==3 ? 1 : 0);
  }
}